// round 2
// baseline (speedup 1.0000x reference)
#include <cuda_runtime.h>
#include <cuda_bf16.h>
#include <cstdint>

// Problem constants
#define L_COMP 16384
#define D      1024
#define D4     (D/4)          // 256 float4 per row
#define L_FULL 32768
#define EPS    1e-4f

// Chunking
#define C   64                // chunk length along L
#define NC  256               // L_COMP / C
#define TPB 256               // one thread = 4 channels (float4)

// Scratch (device globals: no allocation allowed)
__device__ float g_S[NC * D];        // chunk aggregates (scan-from-zero endpoint)
__device__ float g_Zc[NC * D];       // carry-in (exclusive prefix state) per chunk
__device__ int   g_pos[L_COMP + 1];  // segment start positions in full sequence

__device__ __forceinline__ float clipp(float v) {
    return fminf(fmaxf(v, EPS), 1.0f - EPS);
}

// ---------------------------------------------------------------------------
// Pass 1: per-chunk local scan from zero -> endpoint aggregate S[c][d]
// grid = NC blocks, TPB threads, each thread owns 4 channels (float4)
// ---------------------------------------------------------------------------
__global__ void __launch_bounds__(TPB) pass1_kernel(const float* __restrict__ x,
                                                    const float* __restrict__ p) {
    const int c   = blockIdx.x;
    const int tid = threadIdx.x;

    __shared__ float psm[C];
    __shared__ float adm[C];
    for (int i = tid; i < C; i += TPB) {
        float pv = clipp(p[c * C + i]);
        psm[i] = pv;
        adm[i] = 1.0f - pv;
    }
    __syncthreads();

    const float4* __restrict__ x4 = (const float4*)x;
    float4 s = make_float4(0.f, 0.f, 0.f, 0.f);
    const int base = c * C;

#pragma unroll 4
    for (int l = 0; l < C; l++) {
        float4 xv = x4[(base + l) * D4 + tid];
        float a = adm[l], pv = psm[l];
        s.x = fmaf(a, s.x, pv * xv.x);
        s.y = fmaf(a, s.y, pv * xv.y);
        s.z = fmaf(a, s.z, pv * xv.z);
        s.w = fmaf(a, s.w, pv * xv.w);
    }
    ((float4*)g_S)[c * D4 + tid] = s;
}

// ---------------------------------------------------------------------------
// Boundary kernel: block-wide scan of b (L_FULL ints) -> segment starts g_pos
// single block of 1024 threads, each handles 32 consecutive elements
// ---------------------------------------------------------------------------
__global__ void __launch_bounds__(1024) boundary_kernel(const int* __restrict__ b) {
    const int tid  = threadIdx.x;
    const int lane = tid & 31;
    const int wid  = tid >> 5;
    const int base = tid * 32;

    int cnt = 0;
#pragma unroll 8
    for (int i = 0; i < 32; i++) cnt += b[base + i];

    // inclusive warp scan
    int v = cnt;
#pragma unroll
    for (int o = 1; o < 32; o <<= 1) {
        int n = __shfl_up_sync(0xffffffffu, v, o);
        if (lane >= o) v += n;
    }
    __shared__ int ws[32];
    if (lane == 31) ws[wid] = v;
    __syncthreads();
    if (wid == 0) {
        int w = ws[lane];
#pragma unroll
        for (int o = 1; o < 32; o <<= 1) {
            int n = __shfl_up_sync(0xffffffffu, w, o);
            if (lane >= o) w += n;
        }
        ws[lane] = w;
    }
    __syncthreads();

    int excl = v - cnt + (wid > 0 ? ws[wid - 1] : 0);

    int run = excl;
#pragma unroll 8
    for (int i = 0; i < 32; i++) {
        if (b[base + i]) {
            g_pos[run] = base + i;
            run++;
        }
    }
    if (tid == 0) g_pos[L_COMP] = L_FULL;
}

// ---------------------------------------------------------------------------
// Pass 2: cross-chunk serial recurrence -> per-chunk carry-ins g_Zc
// single block, 1024 threads (one per channel)
// ---------------------------------------------------------------------------
__global__ void __launch_bounds__(1024) pass2_kernel(const float* __restrict__ p) {
    const int tid = threadIdx.x;   // channel d

    __shared__ float Psm[NC];
    // chunk decay products (channel-independent): threads 0..NC-1 each do one chunk
    if (tid < NC) {
        float prod = 1.0f;
#pragma unroll 8
        for (int l = 0; l < C; l++)
            prod *= (1.0f - clipp(p[tid * C + l]));
        Psm[tid] = prod;
    }
    __syncthreads();

    float z = 0.0f;
#pragma unroll 8
    for (int cidx = 0; cidx < NC; cidx++) {
        g_Zc[cidx * D + tid] = z;                       // exclusive carry-in
        z = fmaf(Psm[cidx], z, g_S[cidx * D + tid]);
    }
}

// ---------------------------------------------------------------------------
// Pass 3: per-chunk scan seeded by carry-in; fused segment-replicated store
// grid = NC blocks, TPB threads, float4 per thread
// ---------------------------------------------------------------------------
__global__ void __launch_bounds__(TPB) pass3_kernel(const float* __restrict__ x,
                                                    const float* __restrict__ p,
                                                    float* __restrict__ out) {
    const int c   = blockIdx.x;
    const int tid = threadIdx.x;

    __shared__ float psm[C];
    __shared__ float adm[C];
    __shared__ int   possm[C + 1];
    for (int i = tid; i < C; i += TPB) {
        float pv = clipp(p[c * C + i]);
        psm[i] = pv;
        adm[i] = 1.0f - pv;
    }
    for (int i = tid; i < C + 1; i += TPB)
        possm[i] = g_pos[c * C + i];
    __syncthreads();

    const float4* __restrict__ x4   = (const float4*)x;
    float4* __restrict__       out4 = (float4*)out;

    float4 z = ((const float4*)g_Zc)[c * D4 + tid];
    const int base = c * C;

    for (int l = 0; l < C; l++) {
        float4 xv = x4[(base + l) * D4 + tid];
        float a = adm[l], pv = psm[l];
        z.x = fmaf(a, z.x, pv * xv.x);
        z.y = fmaf(a, z.y, pv * xv.y);
        z.z = fmaf(a, z.z, pv * xv.z);
        z.w = fmaf(a, z.w, pv * xv.w);

        int s = possm[l];
        int e = possm[l + 1];
        for (int f = s; f < e; f++)
            out4[f * D4 + tid] = z;
    }
}

// ---------------------------------------------------------------------------
extern "C" void kernel_launch(void* const* d_in, const int* in_sizes, int n_in,
                              void* d_out, int out_size) {
    const float* x = (const float*)d_in[0];   // (1, L_COMP, D) f32
    const float* p = (const float*)d_in[1];   // (L_COMP,)      f32
    const int*   b = (const int*)d_in[2];     // (1, L_FULL)    i32
    float*       o = (float*)d_out;           // (1, L_FULL, D) f32

    pass1_kernel<<<NC, TPB>>>(x, p);
    boundary_kernel<<<1, 1024>>>(b);
    pass2_kernel<<<1, 1024>>>(p);
    pass3_kernel<<<NC, TPB>>>(x, p, o);
}